// round 15
// baseline (speedup 1.0000x reference)
#include <cuda_runtime.h>
#include <cuda_bf16.h>
#include <math.h>
#include <stdint.h>

constexpr int kB  = 8;
constexpr int kC  = 64;
constexpr int kNC = 128;
constexpr int kH  = 192;
constexpr int kW  = 384;
constexpr int kHW = kH * kW;                    // 73728
constexpr float kScale = 0.08838834764831845f;  // 1/sqrt(128)

// ---------------- scratch (device globals; no runtime allocation) ----------------
__device__ __nv_bfloat16 g_nl[kB*kC*kHW];
__device__ __nv_bfloat16 g_nr[kB*kC*kHW];
__device__ __nv_bfloat16 g_P0[kB*kNC*kHW];
__device__ __nv_bfloat16 g_P1[kB*kNC*kHW];
__device__ __nv_bfloat16 g_P2[kB*kNC*kHW];
__device__ __nv_bfloat16 g_P3[kB*kNC*kHW];
__device__ __nv_bfloat16 g_P4[kB*kNC*kHW];
__device__ __nv_bfloat16 g_Vl[kB*kNC*kHW];
__device__ __nv_bfloat16 g_Kl[kB*kNC*kHW];
__device__ __nv_bfloat16 g_Qm[kB*kNC*kHW];
__device__ __nv_bfloat16 g_Kr[kB*kNC*kHW];
__device__ __nv_bfloat16 g_Vr[kB*kNC*kHW];
__device__ __nv_bfloat16 g_Ol[kB*kNC*kHW];
__device__ __nv_bfloat16 g_Or[kB*kNC*kHW];
__device__ __nv_bfloat16 g_Wbf[65536];   // bf16 copies of w1..w7

// ---------------- helpers ----------------
__device__ __forceinline__ void ldsm4(uint32_t* r, uint32_t addr) {
  asm volatile("ldmatrix.sync.aligned.m8n8.x4.shared.b16 {%0,%1,%2,%3}, [%4];"
    : "=r"(r[0]), "=r"(r[1]), "=r"(r[2]), "=r"(r[3]) : "r"(addr));
}
__device__ __forceinline__ void ldsm4t(uint32_t* r, uint32_t addr) {
  asm volatile("ldmatrix.sync.aligned.m8n8.x4.trans.shared.b16 {%0,%1,%2,%3}, [%4];"
    : "=r"(r[0]), "=r"(r[1]), "=r"(r[2]), "=r"(r[3]) : "r"(addr));
}
__device__ __forceinline__ void mma16816(float* c, const uint32_t* a, uint32_t b0, uint32_t b1) {
  asm volatile("mma.sync.aligned.m16n8k16.row.col.f32.bf16.bf16.f32 "
    "{%0,%1,%2,%3}, {%4,%5,%6,%7}, {%8,%9}, {%0,%1,%2,%3};"
    : "+f"(c[0]), "+f"(c[1]), "+f"(c[2]), "+f"(c[3])
    : "r"(a[0]), "r"(a[1]), "r"(a[2]), "r"(a[3]), "r"(b0), "r"(b1));
}
__device__ __forceinline__ __nv_bfloat162 pack_bf2(float a, float b) {
  return __floats2bfloat162_rn(a, b);
}
__device__ __forceinline__ void cp16(uint32_t dst, const void* src) {
  asm volatile("cp.async.cg.shared.global [%0], [%1], 16;" :: "r"(dst), "l"(src));
}
__device__ __forceinline__ void cp_commit() { asm volatile("cp.async.commit_group;"); }
template<int N> __device__ __forceinline__ void cp_wait() {
  asm volatile("cp.async.wait_group %0;" :: "n"(N));
}

struct ConvArgs {
  const __nv_bfloat16* inA;
  const __nv_bfloat16* inB;
  const __nv_bfloat16* w;      // bf16, pre-converted
  const float* bias;
  const float* res;
  float* outF;
  __nv_bfloat16* outB;
};
struct DwArgs {
  const __nv_bfloat16* in;
  const float* w;
  const float* bias;
  __nv_bfloat16* out;
};

// ---------------- weight pre-conversion (fp32 -> bf16), one shot ----------------
__global__ __launch_bounds__(256) void wconv_kernel(
    const float* __restrict__ w1, const float* __restrict__ w2,
    const float* __restrict__ w3, const float* __restrict__ w4,
    const float* __restrict__ w5, const float* __restrict__ w6,
    const float* __restrict__ w7) {
  int i = blockIdx.x*256 + threadIdx.x;              // 65536 total
  const float* src; int off;
  if      (i < 8192)  { src = w1; off = 0;     }
  else if (i < 16384) { src = w2; off = 8192;  }
  else if (i < 32768) { src = w3; off = 16384; }
  else if (i < 40960) { src = w4; off = 32768; }
  else if (i < 49152) { src = w5; off = 40960; }
  else if (i < 57344) { src = w6; off = 49152; }
  else                { src = w7; off = 57344; }
  g_Wbf[i] = __float2bfloat16(src[i - off]);
}

// ---------------- LayerNorm2d (both sides in one launch), bf16 out ----------------
__global__ __launch_bounds__(256) void ln_kernel(
    const float* __restrict__ x0, const float* __restrict__ x1,
    const float* __restrict__ g0, const float* __restrict__ be0,
    const float* __restrict__ g1, const float* __restrict__ be1,
    __nv_bfloat16* __restrict__ o0, __nv_bfloat16* __restrict__ o1) {
  int side = blockIdx.y;
  const float* x   = side ? x1 : x0;
  const float* gam = side ? g1 : g0;
  const float* bet = side ? be1 : be0;
  __nv_bfloat16* out = side ? o1 : o0;
  int idx = blockIdx.x * 256 + threadIdx.x;     // over B*HW
  int b = idx / kHW, p = idx % kHW;
  const float* xp = x + (size_t)b*kC*kHW + p;
  float v[kC];
  float s = 0.f;
#pragma unroll
  for (int c = 0; c < kC; c++) { v[c] = xp[(size_t)c*kHW]; s += v[c]; }
  float mu = s * (1.f/kC);
  float q = 0.f;
#pragma unroll
  for (int c = 0; c < kC; c++) { float d = v[c]-mu; q += d*d; }
  float rstd = rsqrtf(q*(1.f/kC) + 1e-6f);
  __nv_bfloat16* op = out + (size_t)b*kC*kHW + p;
#pragma unroll
  for (int c = 0; c < kC; c++)
    op[(size_t)c*kHW] = __float2bfloat16((v[c]-mu)*rstd*__ldg(&gam[c]) + __ldg(&bet[c]));
}

// ---------------- conv1x1 v5: weight-persistent, 64-px tiles, 4x2 warp grid ----------------
// Block = COUT x 256px as 4 sequential 64-px tiles; K in 32-row cp.async chunks (2 bufs).
// 8 warps as 4x2: warp tile = (COUT/4) rows x 32 px.  W smem dup x2, X dup x4.
template<int COUT, int KDIM, bool DUAL, bool RES>
__global__ __launch_bounds__(256) void conv1x1_mma_kernel(
    ConvArgs c0, ConvArgs c1, ConvArgs c2, ConvArgs c3) {
  constexpr int KCH = KDIM/32;             // k chunks per tile
  constexpr int PT  = 4;                   // px tiles per block
  constexpr int NS  = PT*KCH;              // total pipeline stages
  constexpr int KP  = KDIM + 8;
  constexpr int MF  = COUT/64;             // m-frags per warp (2 or 1)
  __shared__ __nv_bfloat16 sW[COUT*KP];
  __shared__ __nv_bfloat16 sX[2*32*72];

  ConvArgs A = c0;
  { int y = blockIdx.y; if (y == 1) A = c1; else if (y == 2) A = c2; else if (y == 3) A = c3; }
  int b  = blockIdx.z;
  int p0 = blockIdx.x * 256;
  int t  = threadIdx.x, warp = t >> 5, lane = t & 31;
  int wm = warp >> 1, wn = warp & 1;

  uint32_t sWb = (uint32_t)__cvta_generic_to_shared(sW);
  uint32_t sXb = (uint32_t)__cvta_generic_to_shared(sX);

  // one 32-row x 64-px chunk fill: exactly 1 cp16 per thread
  auto fill = [&](int buf, int pt, int kk) {
    int row = t >> 3, cg = t & 7;
    int kg = kk*32 + row;
    const __nv_bfloat16* src;
    if (DUAL) src = (kg < kC) ? (A.inA + ((size_t)b*kC + kg)*kHW)
                              : (A.inB + ((size_t)b*kC + (kg-kC))*kHW);
    else      src = A.inA + ((size_t)b*KDIM + kg)*kHW;
    cp16(sXb + (uint32_t)(buf*32*72 + row*72 + cg*8)*2, src + p0 + pt*64 + cg*8);
  };

  fill(0, 0, 0); cp_commit();
  // weights resident for the whole block (overlaps the async fill)
  for (int i = 8*t; i < COUT*KDIM; i += 2048) {
    int o = i / KDIM, k = i - o*KDIM;
    *(uint4*)&sW[o*KP + k] = *(const uint4*)(A.w + i);
  }

  float acc[MF][4][4];
#pragma unroll
  for (int i = 0; i < MF; i++)
#pragma unroll
    for (int j = 0; j < 4; j++)
#pragma unroll
      for (int k = 0; k < 4; k++) acc[i][j][k] = 0.f;

  for (int s = 0; s < NS; s++) {
    int pt = s / KCH, kk = s % KCH;
    if (s+1 < NS) { fill((s+1)&1, (s+1)/KCH, (s+1)%KCH); cp_commit(); cp_wait<1>(); }
    else          { cp_wait<0>(); }
    __syncthreads();
    uint32_t xbase = sXb + (uint32_t)((s&1)*32*72)*2;
#pragma unroll
    for (int ks = 0; ks < 2; ks++) {
      int wcol = kk*32 + ks*16 + (lane >> 4)*8;
      uint32_t a[MF][4];
#pragma unroll
      for (int mf = 0; mf < MF; mf++) {
        int row = wm*(COUT/4) + mf*16 + (lane & 15);
        ldsm4(a[mf], sWb + (uint32_t)(row*KP + wcol)*2);
      }
      uint32_t bf[2][4];
#pragma unroll
      for (int nb = 0; nb < 2; nb++) {
        int xrow = ks*16 + ((lane >> 3) & 1)*8 + (lane & 7);
        int ncol = wn*32 + nb*16 + (lane >> 4)*8;
        ldsm4t(bf[nb], xbase + (uint32_t)(xrow*72 + ncol)*2);
      }
#pragma unroll
      for (int mf = 0; mf < MF; mf++)
#pragma unroll
        for (int nf = 0; nf < 4; nf++)
          mma16816(acc[mf][nf], a[mf], bf[nf>>1][(nf&1)*2], bf[nf>>1][(nf&1)*2+1]);
    }
    if (kk == KCH-1) {
      int px = p0 + pt*64;
#pragma unroll
      for (int mf = 0; mf < MF; mf++) {
        int row = wm*(COUT/4) + mf*16 + (lane >> 2);
        float bv0 = __ldg(&A.bias[row]);
        float bv1 = __ldg(&A.bias[row+8]);
#pragma unroll
        for (int nf = 0; nf < 4; nf++) {
          int col = wn*32 + nf*8 + (lane & 3)*2;
          size_t o0 = ((size_t)b*COUT + row)*kHW + px + col;
          size_t o1 = o0 + (size_t)8*kHW;
          if (RES) {
            float2 r0 = *(const float2*)(A.res + o0);
            float2 r1 = *(const float2*)(A.res + o1);
            *(float2*)(A.outF + o0) = make_float2(acc[mf][nf][0]+bv0+r0.x, acc[mf][nf][1]+bv0+r0.y);
            *(float2*)(A.outF + o1) = make_float2(acc[mf][nf][2]+bv1+r1.x, acc[mf][nf][3]+bv1+r1.y);
          } else {
            *(__nv_bfloat162*)(A.outB + o0) = pack_bf2(acc[mf][nf][0]+bv0, acc[mf][nf][1]+bv0);
            *(__nv_bfloat162*)(A.outB + o1) = pack_bf2(acc[mf][nf][2]+bv1, acc[mf][nf][3]+bv1);
          }
          acc[mf][nf][0] = acc[mf][nf][1] = acc[mf][nf][2] = acc[mf][nf][3] = 0.f;
        }
      }
    }
    __syncthreads();
  }
}

// ---------------- depthwise 3x3, tiled smem, vectorized taps, 5 branches/launch ----------------
__global__ __launch_bounds__(256) void dwconv_kernel(
    DwArgs d0, DwArgs d1, DwArgs d2, DwArgs d3, DwArgs d4) {
  DwArgs a = d0;
  int z = blockIdx.z;
  if (z == 1) a = d1; else if (z == 2) a = d2; else if (z == 3) a = d3; else if (z == 4) a = d4;

  int bc = blockIdx.y;
  int c  = bc & (kNC-1);
  int h0 = blockIdx.x * 8;
  const __nv_bfloat16* ip = a.in + (size_t)bc*kHW;
  __nv_bfloat16* op = a.out + (size_t)bc*kHW;
  __shared__ __nv_bfloat16 tile[10][400];   // data at cols [8,392); halo zeroed
  int t = threadIdx.x;

  for (int i = t; i < 160; i += 256) {
    int r = i >> 4, j = i & 15;
    tile[r][(j < 8) ? j : 384 + j] = __float2bfloat16(0.f);
  }
  for (int i = t; i < 480; i += 256) {
    int r = i / 48, cg = i - r*48;
    int h = h0 - 1 + r;
    uint4 v = make_uint4(0u, 0u, 0u, 0u);
    if (h >= 0 && h < kH) v = *(const uint4*)(ip + (size_t)h*kW + cg*8);
    *(uint4*)&tile[r][8 + cg*8] = v;
  }
  __syncthreads();

  float wr[9];
#pragma unroll
  for (int j = 0; j < 9; j++) wr[j] = __ldg(&a.w[c*9 + j]);
  float bv = __ldg(&a.bias[c]);

#pragma unroll
  for (int i = 0; i < 6; i++) {
    int p = 2*(t + 256*i);              // 3072 px per block, x even
    int row = p / 384, x = p - row*384;
    float a0 = bv, a1 = bv;
#pragma unroll
    for (int dy = 0; dy < 3; dy++) {
      // need logical cols x-1..x+2 = tile cols 7+x..10+x; aligned bf162 loads
      __nv_bfloat162 v0 = *(__nv_bfloat162*)&tile[row+dy][6 + x];   // (.y = col 7+x)
      __nv_bfloat162 v1 = *(__nv_bfloat162*)&tile[row+dy][8 + x];   // cols 8+x, 9+x
      __nv_bfloat162 v2 = *(__nv_bfloat162*)&tile[row+dy][10 + x];  // (.x = col 10+x)
      float l  = __bfloat162float(v0.y);
      float c0 = __bfloat162float(v1.x);
      float c1 = __bfloat162float(v1.y);
      float r_ = __bfloat162float(v2.x);
      float w0 = wr[dy*3+0], w1 = wr[dy*3+1], w2 = wr[dy*3+2];
      a0 += w0*l  + w1*c0 + w2*c1;
      a1 += w0*c0 + w1*c1 + w2*r_;
    }
    *(__nv_bfloat162*)(op + (size_t)(h0+row)*kW + x) = pack_bf2(a0, a1);
  }
}

// ---------------- fused attention: O = softmax(Q K^T * scale) @ V ----------------
// Phase 1: Q(64x32)+K(192x32) chunks streamed via cp.async double-buffered ring;
// S(64x192) in regs -> softmax -> bf16 A into sA.
// Phase 2: O(64x384) in three 128-wide n-chunks; V double-buffered (overlays ring).
__global__ __launch_bounds__(128) void attn_kernel() {
  __shared__ __nv_bfloat16 sA[64*200];        // softmaxed A, stride 200
  __shared__ __nv_bfloat16 sBuf[2*256*40];    // ring: Q(64)+K(192) rows, stride 40; phase2 V ring
  int bc = blockIdx.y, side = blockIdx.z;
  const __nv_bfloat16* qb = g_Qm + (size_t)bc*kHW;
  const __nv_bfloat16* km = (side == 0 ? g_Kr : g_Kl) + (size_t)bc*kHW;
  const __nv_bfloat16* vb = (side == 0 ? g_Vl : g_Vr) + (size_t)bc*kHW;
  __nv_bfloat16* ob = (side == 0 ? g_Ol : g_Or) + (size_t)bc*kHW;
  int m0 = blockIdx.x * 64;
  int t = threadIdx.x, warp = t >> 5, lane = t & 31;

  uint32_t sAb = (uint32_t)__cvta_generic_to_shared(sA);
  uint32_t sBb = (uint32_t)__cvta_generic_to_shared(sBuf);

  // ---- phase 1 ----
  {
    auto fillQK = [&](int buf, int kb) {
      const __nv_bfloat16* qsrc = qb + (size_t)m0*kW + kb*32;
      const __nv_bfloat16* ksrc = km + kb*32;
      for (int i = t; i < 1024; i += 128) {
        int row = i >> 2, cg = i & 3;
        const __nv_bfloat16* src = (row < 64) ? (qsrc + (size_t)row*kW + cg*8)
                                              : (ksrc + (size_t)(row-64)*kW + cg*8);
        cp16(sBb + (uint32_t)(buf*10240 + row*40 + cg*8)*2, src);
      }
    };

    fillQK(0, 0); cp_commit();

    float acc[24][4];
#pragma unroll
    for (int i = 0; i < 24; i++)
#pragma unroll
      for (int j = 0; j < 4; j++) acc[i][j] = 0.f;

    for (int kb = 0; kb < 12; kb++) {          // 12 chunks of 32 k
      if (kb < 11) { fillQK((kb+1)&1, kb+1); cp_commit(); cp_wait<1>(); }
      else         { cp_wait<0>(); }
      __syncthreads();
      uint32_t qbase = sBb + (uint32_t)((kb&1)*10240)*2;
      uint32_t kbase = qbase + (uint32_t)(64*40)*2;
#pragma unroll
      for (int ks = 0; ks < 2; ks++) {
        int k0 = ks*16;
        uint32_t a[4];
        {
          int row = warp*16 + (lane & 15);
          int col = k0 + (lane >> 4)*8;
          ldsm4(a, qbase + (uint32_t)(row*40 + col)*2);
        }
        uint32_t bf[12][4];
#pragma unroll
        for (int nb = 0; nb < 12; nb++) {
          int nrow = nb*16 + (lane >> 4)*8 + (lane & 7);
          int col  = k0 + ((lane >> 3) & 1)*8;
          ldsm4(bf[nb], kbase + (uint32_t)(nrow*40 + col)*2);
        }
#pragma unroll
        for (int nf = 0; nf < 24; nf++)
          mma16816(acc[nf], a, bf[nf>>1][(nf&1)*2], bf[nf>>1][(nf&1)*2+1]);
      }
      __syncthreads();
    }

#pragma unroll
    for (int nf = 0; nf < 24; nf++)
#pragma unroll
      for (int j = 0; j < 4; j++) acc[nf][j] *= kScale;

    float mx0 = -1e30f, mx1 = -1e30f;
#pragma unroll
    for (int nf = 0; nf < 24; nf++) {
      mx0 = fmaxf(mx0, fmaxf(acc[nf][0], acc[nf][1]));
      mx1 = fmaxf(mx1, fmaxf(acc[nf][2], acc[nf][3]));
    }
#pragma unroll
    for (int o = 1; o <= 2; o <<= 1) {
      mx0 = fmaxf(mx0, __shfl_xor_sync(0xffffffffu, mx0, o));
      mx1 = fmaxf(mx1, __shfl_xor_sync(0xffffffffu, mx1, o));
    }
    float s0 = 0.f, s1 = 0.f;
#pragma unroll
    for (int nf = 0; nf < 24; nf++) {
      acc[nf][0] = __expf(acc[nf][0]-mx0); s0 += acc[nf][0];
      acc[nf][1] = __expf(acc[nf][1]-mx0); s0 += acc[nf][1];
      acc[nf][2] = __expf(acc[nf][2]-mx1); s1 += acc[nf][2];
      acc[nf][3] = __expf(acc[nf][3]-mx1); s1 += acc[nf][3];
    }
#pragma unroll
    for (int o = 1; o <= 2; o <<= 1) {
      s0 += __shfl_xor_sync(0xffffffffu, s0, o);
      s1 += __shfl_xor_sync(0xffffffffu, s1, o);
    }
    float i0 = 1.f/s0, i1 = 1.f/s1;

    int r0 = warp*16 + (lane >> 2);
#pragma unroll
    for (int nf = 0; nf < 24; nf++) {
      int c = nf*8 + (lane & 3)*2;
      *(__nv_bfloat162*)&sA[r0*200 + c]     = pack_bf2(acc[nf][0]*i0, acc[nf][1]*i0);
      *(__nv_bfloat162*)&sA[(r0+8)*200 + c] = pack_bf2(acc[nf][2]*i1, acc[nf][3]*i1);
    }
  }
  __syncthreads();

  // ---- phase 2: O = A @ V, warp grid 2x2, n-chunks of 128, V double-buffered ----
  int wm = warp >> 1, wn = warp & 1;
#pragma unroll
  for (int n0 = 0; n0 < kW; n0 += 128) {
    float oac[2][8][4];
#pragma unroll
    for (int i = 0; i < 2; i++)
#pragma unroll
      for (int j = 0; j < 8; j++)
#pragma unroll
        for (int k = 0; k < 4; k++) oac[i][j][k] = 0.f;

    for (int i = t; i < 512; i += 128) {
      int row = i >> 4, cg = i & 15;
      cp16(sBb + (uint32_t)(row*136 + cg*8)*2, vb + (size_t)row*kW + n0 + cg*8);
    }
    cp_commit();

    for (int kc = 0; kc < 6; kc++) {
      if (kc < 5) {
        uint32_t dst = sBb + (uint32_t)(((kc+1)&1)*32*136)*2;
        const __nv_bfloat16* vsrc = vb + (size_t)(kc+1)*32*kW + n0;
        for (int i = t; i < 512; i += 128) {
          int row = i >> 4, cg = i & 15;
          cp16(dst + (uint32_t)(row*136 + cg*8)*2, vsrc + (size_t)row*kW + cg*8);
        }
        cp_commit();
        cp_wait<1>();
      } else {
        cp_wait<0>();
      }
      __syncthreads();
      uint32_t vbase = sBb + (uint32_t)((kc&1)*32*136)*2;
#pragma unroll
      for (int ks = 0; ks < 2; ks++) {
        int k0 = ks*16;
        uint32_t a[2][4];
#pragma unroll
        for (int mf = 0; mf < 2; mf++) {
          int row = wm*32 + mf*16 + (lane & 15);
          int col = kc*32 + k0 + (lane >> 4)*8;
          ldsm4(a[mf], sAb + (uint32_t)(row*200 + col)*2);
        }
        uint32_t b[4][4];
#pragma unroll
        for (int nb = 0; nb < 4; nb++) {
          int krow = k0 + ((lane >> 3) & 1)*8 + (lane & 7);
          int ncol = wn*64 + nb*16 + (lane >> 4)*8;
          ldsm4t(b[nb], vbase + (uint32_t)(krow*136 + ncol)*2);
        }
#pragma unroll
        for (int mf = 0; mf < 2; mf++)
#pragma unroll
          for (int nf = 0; nf < 8; nf++)
            mma16816(oac[mf][nf], a[mf], b[nf>>1][(nf&1)*2], b[nf>>1][(nf&1)*2+1]);
      }
      __syncthreads();
    }
#pragma unroll
    for (int mf = 0; mf < 2; mf++)
#pragma unroll
      for (int nf = 0; nf < 8; nf++) {
        int r = m0 + wm*32 + mf*16 + (lane >> 2);
        int c = n0 + wn*64 + nf*8 + (lane & 3)*2;
        *(__nv_bfloat162*)(ob + (size_t)r*kW + c)     = pack_bf2(oac[mf][nf][0], oac[mf][nf][1]);
        *(__nv_bfloat162*)(ob + (size_t)(r+8)*kW + c) = pack_bf2(oac[mf][nf][2], oac[mf][nf][3]);
      }
  }
}

// ---------------- launch ----------------
extern "C" void kernel_launch(void* const* d_in, const int* in_sizes, int n_in,
                              void* d_out, int out_size) {
  const float* x_l   = (const float*)d_in[0];
  const float* x_r   = (const float*)d_in[1];
  const float* ln1_g = (const float*)d_in[2];
  const float* ln1_b = (const float*)d_in[3];
  const float* ln2_g = (const float*)d_in[4];
  const float* ln2_b = (const float*)d_in[5];
  const float* w1 = (const float*)d_in[6];   const float* b1 = (const float*)d_in[7];
  const float* w2 = (const float*)d_in[8];   const float* b2 = (const float*)d_in[9];
  const float* w3 = (const float*)d_in[10];  const float* b3 = (const float*)d_in[11];
  const float* w4 = (const float*)d_in[12];  const float* b4 = (const float*)d_in[13];
  const float* w5 = (const float*)d_in[14];  const float* b5 = (const float*)d_in[15];
  const float* dw1 = (const float*)d_in[16]; const float* db1 = (const float*)d_in[17];
  const float* dw2 = (const float*)d_in[18]; const float* db2 = (const float*)d_in[19];
  const float* dw3 = (const float*)d_in[20]; const float* db3 = (const float*)d_in[21];
  const float* dw4 = (const float*)d_in[22]; const float* db4 = (const float*)d_in[23];
  const float* dw5 = (const float*)d_in[24]; const float* db5 = (const float*)d_in[25];
  const float* w6 = (const float*)d_in[26];  const float* b6 = (const float*)d_in[27];
  const float* w7 = (const float*)d_in[28];  const float* b7 = (const float*)d_in[29];
  float* out = (float*)d_out;

  __nv_bfloat16 *nl, *nr, *P0, *P1, *P2, *P3, *P4, *Vl, *Kl, *Qm, *Kr, *Vr, *Ol, *Or, *Wbf;
  cudaGetSymbolAddress((void**)&nl, g_nl);
  cudaGetSymbolAddress((void**)&nr, g_nr);
  cudaGetSymbolAddress((void**)&P0, g_P0);
  cudaGetSymbolAddress((void**)&P1, g_P1);
  cudaGetSymbolAddress((void**)&P2, g_P2);
  cudaGetSymbolAddress((void**)&P3, g_P3);
  cudaGetSymbolAddress((void**)&P4, g_P4);
  cudaGetSymbolAddress((void**)&Vl, g_Vl);
  cudaGetSymbolAddress((void**)&Kl, g_Kl);
  cudaGetSymbolAddress((void**)&Qm, g_Qm);
  cudaGetSymbolAddress((void**)&Kr, g_Kr);
  cudaGetSymbolAddress((void**)&Vr, g_Vr);
  cudaGetSymbolAddress((void**)&Ol, g_Ol);
  cudaGetSymbolAddress((void**)&Or, g_Or);
  cudaGetSymbolAddress((void**)&Wbf, g_Wbf);

  // 0. weights -> bf16 arena
  wconv_kernel<<<256, 256>>>(w1, w2, w3, w4, w5, w6, w7);

  // 1. LayerNorm2d (both sides)
  ln_kernel<<<dim3(kB*kHW/256, 2), 256>>>(x_l, x_r, ln1_g, ln1_b, ln2_g, ln2_b, nl, nr);

  // 2. conv1x1 branches: four single-input branches in one launch, dual-input alone
  ConvArgs a1 = { nl, nullptr, Wbf,         b1, nullptr, nullptr, P0 };
  ConvArgs a2 = { nl, nullptr, Wbf + 8192,  b2, nullptr, nullptr, P1 };
  ConvArgs a3 = { nl, nr,      Wbf + 16384, b3, nullptr, nullptr, P2 };
  ConvArgs a4 = { nr, nullptr, Wbf + 32768, b4, nullptr, nullptr, P3 };
  ConvArgs a5 = { nr, nullptr, Wbf + 40960, b5, nullptr, nullptr, P4 };
  conv1x1_mma_kernel<kNC, kC, false, false><<<dim3(kHW/256, 4, kB), 256>>>(a1, a2, a4, a5);
  conv1x1_mma_kernel<kNC, 2*kC, true, false><<<dim3(kHW/256, 1, kB), 256>>>(a3, a3, a3, a3);

  // 3. all five depthwise 3x3 convs in one launch
  DwArgs dA = { P0, dw1, db1, Vl };
  DwArgs dB = { P1, dw2, db2, Kl };
  DwArgs dC = { P2, dw3, db3, Qm };
  DwArgs dD = { P3, dw4, db4, Kr };
  DwArgs dE = { P4, dw5, db5, Vr };
  dwconv_kernel<<<dim3(kH/8, kB*kNC, 5), 256>>>(dA, dB, dC, dD, dE);

  // 4. fused attention (S + softmax + O)
  attn_kernel<<<dim3(3, kB*kNC, 2), 128>>>();

  // 5. final conv1x1 + residual (both sides), fp32 out
  ConvArgs f0 = { Ol, nullptr, Wbf + 49152, b6, x_l, out, nullptr };
  ConvArgs f1 = { Or, nullptr, Wbf + 57344, b7, x_r, out + (size_t)kB*kC*kHW, nullptr };
  conv1x1_mma_kernel<kC, kNC, false, true><<<dim3(kHW/256, 2, kB), 256>>>(f0, f1, f0, f1);
}

// round 16
// speedup vs baseline: 1.1229x; 1.1229x over previous
#include <cuda_runtime.h>
#include <cuda_bf16.h>
#include <math.h>
#include <stdint.h>

constexpr int kB  = 8;
constexpr int kC  = 64;
constexpr int kNC = 128;
constexpr int kH  = 192;
constexpr int kW  = 384;
constexpr int kHW = kH * kW;                    // 73728
constexpr float kScale = 0.08838834764831845f;  // 1/sqrt(128)

// ---------------- scratch (device globals; no runtime allocation) ----------------
__device__ __nv_bfloat16 g_nl[kB*kC*kHW];
__device__ __nv_bfloat16 g_nr[kB*kC*kHW];
__device__ __nv_bfloat16 g_P2[kB*kNC*kHW];
__device__ __nv_bfloat16 g_Vl[kB*kNC*kHW];
__device__ __nv_bfloat16 g_Kl[kB*kNC*kHW];
__device__ __nv_bfloat16 g_Qm[kB*kNC*kHW];
__device__ __nv_bfloat16 g_Kr[kB*kNC*kHW];
__device__ __nv_bfloat16 g_Vr[kB*kNC*kHW];
__device__ __nv_bfloat16 g_Ol[kB*kNC*kHW];
__device__ __nv_bfloat16 g_Or[kB*kNC*kHW];
__device__ __nv_bfloat16 g_Wbf[65536];   // bf16 copies of w1..w7

// ---------------- helpers ----------------
__device__ __forceinline__ void ldsm4(uint32_t* r, uint32_t addr) {
  asm volatile("ldmatrix.sync.aligned.m8n8.x4.shared.b16 {%0,%1,%2,%3}, [%4];"
    : "=r"(r[0]), "=r"(r[1]), "=r"(r[2]), "=r"(r[3]) : "r"(addr));
}
__device__ __forceinline__ void ldsm4t(uint32_t* r, uint32_t addr) {
  asm volatile("ldmatrix.sync.aligned.m8n8.x4.trans.shared.b16 {%0,%1,%2,%3}, [%4];"
    : "=r"(r[0]), "=r"(r[1]), "=r"(r[2]), "=r"(r[3]) : "r"(addr));
}
__device__ __forceinline__ void mma16816(float* c, const uint32_t* a, uint32_t b0, uint32_t b1) {
  asm volatile("mma.sync.aligned.m16n8k16.row.col.f32.bf16.bf16.f32 "
    "{%0,%1,%2,%3}, {%4,%5,%6,%7}, {%8,%9}, {%0,%1,%2,%3};"
    : "+f"(c[0]), "+f"(c[1]), "+f"(c[2]), "+f"(c[3])
    : "r"(a[0]), "r"(a[1]), "r"(a[2]), "r"(a[3]), "r"(b0), "r"(b1));
}
__device__ __forceinline__ __nv_bfloat162 pack_bf2(float a, float b) {
  return __floats2bfloat162_rn(a, b);
}
__device__ __forceinline__ void cp16(uint32_t dst, const void* src) {
  asm volatile("cp.async.cg.shared.global [%0], [%1], 16;" :: "r"(dst), "l"(src));
}
__device__ __forceinline__ void cp16z(uint32_t dst, const void* src, int nbytes) {
  asm volatile("cp.async.cg.shared.global [%0], [%1], 16, %2;"
    :: "r"(dst), "l"(src), "r"(nbytes));
}
__device__ __forceinline__ void cp_commit() { asm volatile("cp.async.commit_group;"); }
template<int N> __device__ __forceinline__ void cp_wait() {
  asm volatile("cp.async.wait_group %0;" :: "n"(N));
}

struct ConvArgs {
  const __nv_bfloat16* inA;
  const __nv_bfloat16* inB;
  const __nv_bfloat16* w;      // bf16, pre-converted
  const float* bias;
  const float* res;
  float* outF;
  __nv_bfloat16* outB;
};
struct DwArgs {
  const __nv_bfloat16* in;
  const float* w;
  const float* bias;
  __nv_bfloat16* out;
};
struct FArgs {
  const __nv_bfloat16* in;     // 64-ch bf16 input (nl or nr)
  const __nv_bfloat16* w;      // bf16 conv weights [128][64]
  const float* bias;           // conv bias
  const float* dww;            // dw weights [128*9] fp32
  const float* dwb;            // dw bias
  __nv_bfloat16* out;          // dwconv output (Q/K/V tensor)
};

// ---------------- weight pre-conversion (fp32 -> bf16), one shot ----------------
__global__ __launch_bounds__(256) void wconv_kernel(
    const float* __restrict__ w1, const float* __restrict__ w2,
    const float* __restrict__ w3, const float* __restrict__ w4,
    const float* __restrict__ w5, const float* __restrict__ w6,
    const float* __restrict__ w7) {
  int i = blockIdx.x*256 + threadIdx.x;              // 65536 total
  const float* src; int off;
  if      (i < 8192)  { src = w1; off = 0;     }
  else if (i < 16384) { src = w2; off = 8192;  }
  else if (i < 32768) { src = w3; off = 16384; }
  else if (i < 40960) { src = w4; off = 32768; }
  else if (i < 49152) { src = w5; off = 40960; }
  else if (i < 57344) { src = w6; off = 49152; }
  else                { src = w7; off = 57344; }
  g_Wbf[i] = __float2bfloat16(src[i - off]);
}

// ---------------- LayerNorm2d (both sides in one launch), bf16 out ----------------
__global__ __launch_bounds__(256) void ln_kernel(
    const float* __restrict__ x0, const float* __restrict__ x1,
    const float* __restrict__ g0, const float* __restrict__ be0,
    const float* __restrict__ g1, const float* __restrict__ be1,
    __nv_bfloat16* __restrict__ o0, __nv_bfloat16* __restrict__ o1) {
  int side = blockIdx.y;
  const float* x   = side ? x1 : x0;
  const float* gam = side ? g1 : g0;
  const float* bet = side ? be1 : be0;
  __nv_bfloat16* out = side ? o1 : o0;
  int idx = blockIdx.x * 256 + threadIdx.x;     // over B*HW
  int b = idx / kHW, p = idx % kHW;
  const float* xp = x + (size_t)b*kC*kHW + p;
  float v[kC];
  float s = 0.f;
#pragma unroll
  for (int c = 0; c < kC; c++) { v[c] = xp[(size_t)c*kHW]; s += v[c]; }
  float mu = s * (1.f/kC);
  float q = 0.f;
#pragma unroll
  for (int c = 0; c < kC; c++) { float d = v[c]-mu; q += d*d; }
  float rstd = rsqrtf(q*(1.f/kC) + 1e-6f);
  __nv_bfloat16* op = out + (size_t)b*kC*kHW + p;
#pragma unroll
  for (int c = 0; c < kC; c++)
    op[(size_t)c*kHW] = __float2bfloat16((v[c]-mu)*rstd*__ldg(&gam[c]) + __ldg(&bet[c]));
}

// ---------------- fused conv1x1 + dwconv3x3 (K=64 branches) ----------------
// Block = one branch x one batch x an 8x48 output tile. Halo region: 10 rows x 64 cols.
// Phase A: stage X (64ch x 640 halo px) + all weights. Phase B: per 32-oc group,
// HMMA conv over halo px -> sO smem (+bias); then dwconv from sO -> global Q/K/V.
__global__ __launch_bounds__(256) void fused_conv_dw_kernel(
    FArgs f0, FArgs f1, FArgs f2, FArgs f3) {
  constexpr int XS = 648;     // sX stride (rows 4 banks apart -> ldsm conflict-free)
  constexpr int OS = 656;     // sO stride (oc rows 8 banks apart -> dw phase tiles banks)
  __shared__ __nv_bfloat16 sW[128*72];
  __shared__ __nv_bfloat16 sX[64*XS];
  __shared__ __nv_bfloat16 sO[32*OS];

  FArgs A = f0;
  { int y = blockIdx.y; if (y == 1) A = f1; else if (y == 2) A = f2; else if (y == 3) A = f3; }
  int b = blockIdx.z;
  int tile = blockIdx.x;            // 24 row-tiles x 8 col-tiles
  int h0 = (tile >> 3) * 8;
  int x0 = (tile & 7) * 48;
  int t = threadIdx.x, warp = t >> 5, lane = t & 31;

  uint32_t sWb = (uint32_t)__cvta_generic_to_shared(sW);
  uint32_t sXb = (uint32_t)__cvta_generic_to_shared(sX);

  // stage X halo: 64 ch x 10 rows x 64 cols (zero-fill OOB chunks)
  for (int i = t; i < 5120; i += 256) {
    int k = i / 80, rem = i - k*80;
    int hr = rem >> 3, cg = rem & 7;
    int h = h0 - 1 + hr;
    int xg = x0 - 8 + cg*8;
    const __nv_bfloat16* src = A.in + ((size_t)b*kC + k)*kHW + (size_t)h*kW + xg;
    int nb = (h >= 0 && h < kH && xg >= 0 && xg < kW) ? 16 : 0;
    cp16z(sXb + (uint32_t)(k*XS + hr*64 + cg*8)*2, src, nb);
  }
  cp_commit();
  // stage all conv weights (128 x 64)
  for (int i = 8*t; i < 128*64; i += 2048) {
    int o = i >> 6, k = i & 63;
    *(uint4*)&sW[o*72 + k] = *(const uint4*)(A.w + i);
  }
  cp_wait<0>();
  __syncthreads();

  int oclT = t >> 3, tiT = t & 7;      // dw-phase assignment: 32 ocs x 8 threads

  for (int g = 0; g < 4; g++) {
    float acc[2][10][4];
#pragma unroll
    for (int i = 0; i < 2; i++)
#pragma unroll
      for (int j = 0; j < 10; j++)
#pragma unroll
        for (int k = 0; k < 4; k++) acc[i][j][k] = 0.f;

#pragma unroll
    for (int k0 = 0; k0 < 64; k0 += 16) {
      uint32_t a[2][4];
#pragma unroll
      for (int mf = 0; mf < 2; mf++) {
        int row = g*32 + mf*16 + (lane & 15);
        int col = k0 + (lane >> 4)*8;
        ldsm4(a[mf], sWb + (uint32_t)(row*72 + col)*2);
      }
      uint32_t bfr[5][4];
#pragma unroll
      for (int nb = 0; nb < 5; nb++) {
        int xrow = k0 + ((lane >> 3) & 1)*8 + (lane & 7);
        int ncol = warp*80 + nb*16 + (lane >> 4)*8;
        ldsm4t(bfr[nb], sXb + (uint32_t)(xrow*XS + ncol)*2);
      }
#pragma unroll
      for (int mf = 0; mf < 2; mf++)
#pragma unroll
        for (int nf = 0; nf < 10; nf++)
          mma16816(acc[mf][nf], a[mf], bfr[nf>>1][(nf&1)*2], bfr[nf>>1][(nf&1)*2+1]);
    }

    // epilogue: conv + bias -> sO (bf16)
#pragma unroll
    for (int mf = 0; mf < 2; mf++) {
      int ocl = mf*16 + (lane >> 2);
      float bv0 = __ldg(&A.bias[g*32 + ocl]);
      float bv1 = __ldg(&A.bias[g*32 + ocl + 8]);
#pragma unroll
      for (int nf = 0; nf < 10; nf++) {
        int px = warp*80 + nf*8 + (lane & 3)*2;
        *(__nv_bfloat162*)&sO[ocl*OS + px]     = pack_bf2(acc[mf][nf][0]+bv0, acc[mf][nf][1]+bv0);
        *(__nv_bfloat162*)&sO[(ocl+8)*OS + px] = pack_bf2(acc[mf][nf][2]+bv1, acc[mf][nf][3]+bv1);
      }
    }
    __syncthreads();

    // dwconv 3x3 from sO -> global (SAME padding already materialized via halo zeros)
    {
      int ch = g*32 + oclT;
      float wr[9];
#pragma unroll
      for (int j = 0; j < 9; j++) wr[j] = __ldg(&A.dww[ch*9 + j]);
      float dbv = __ldg(&A.dwb[ch]);
      const __nv_bfloat16* srow = &sO[oclT*OS];
      __nv_bfloat16* op = A.out + ((size_t)b*kNC + ch)*kHW;
#pragma unroll
      for (int i = 0; i < 24; i++) {
        int p = i*8 + tiT;               // 0..191 pairs for this oc
        int row = p / 24, cp2 = p - row*24;
        int col = cp2*2;
        float a0 = dbv, a1 = dbv;
#pragma unroll
        for (int dy = 0; dy < 3; dy++) {
          int base = (row+dy)*64 + col + 6;
          __nv_bfloat162 v0 = *(const __nv_bfloat162*)&srow[base];
          __nv_bfloat162 v1 = *(const __nv_bfloat162*)&srow[base + 2];
          __nv_bfloat162 v2 = *(const __nv_bfloat162*)&srow[base + 4];
          float l  = __bfloat162float(v0.y);
          float c0 = __bfloat162float(v1.x);
          float c1 = __bfloat162float(v1.y);
          float r_ = __bfloat162float(v2.x);
          float w0 = wr[dy*3+0], w1 = wr[dy*3+1], w2 = wr[dy*3+2];
          a0 += w0*l  + w1*c0 + w2*c1;
          a1 += w0*c0 + w1*c1 + w2*r_;
        }
        *(__nv_bfloat162*)(op + (size_t)(h0+row)*kW + x0 + col) = pack_bf2(a0, a1);
      }
    }
    __syncthreads();
  }
}

// ---------------- conv1x1 v5: weight-persistent, 64-px tiles, 4x2 warp grid ----------------
template<int COUT, int KDIM, bool DUAL, bool RES>
__global__ __launch_bounds__(256) void conv1x1_mma_kernel(
    ConvArgs c0, ConvArgs c1, ConvArgs c2, ConvArgs c3) {
  constexpr int KCH = KDIM/32;
  constexpr int PT  = 4;
  constexpr int NS  = PT*KCH;
  constexpr int KP  = KDIM + 8;
  constexpr int MF  = COUT/64;
  __shared__ __nv_bfloat16 sW[COUT*KP];
  __shared__ __nv_bfloat16 sX[2*32*72];

  ConvArgs A = c0;
  { int y = blockIdx.y; if (y == 1) A = c1; else if (y == 2) A = c2; else if (y == 3) A = c3; }
  int b  = blockIdx.z;
  int p0 = blockIdx.x * 256;
  int t  = threadIdx.x, warp = t >> 5, lane = t & 31;
  int wm = warp >> 1, wn = warp & 1;

  uint32_t sWb = (uint32_t)__cvta_generic_to_shared(sW);
  uint32_t sXb = (uint32_t)__cvta_generic_to_shared(sX);

  auto fill = [&](int buf, int pt, int kk) {
    int row = t >> 3, cg = t & 7;
    int kg = kk*32 + row;
    const __nv_bfloat16* src;
    if (DUAL) src = (kg < kC) ? (A.inA + ((size_t)b*kC + kg)*kHW)
                              : (A.inB + ((size_t)b*kC + (kg-kC))*kHW);
    else      src = A.inA + ((size_t)b*KDIM + kg)*kHW;
    cp16(sXb + (uint32_t)(buf*32*72 + row*72 + cg*8)*2, src + p0 + pt*64 + cg*8);
  };

  fill(0, 0, 0); cp_commit();
  for (int i = 8*t; i < COUT*KDIM; i += 2048) {
    int o = i / KDIM, k = i - o*KDIM;
    *(uint4*)&sW[o*KP + k] = *(const uint4*)(A.w + i);
  }

  float acc[MF][4][4];
#pragma unroll
  for (int i = 0; i < MF; i++)
#pragma unroll
    for (int j = 0; j < 4; j++)
#pragma unroll
      for (int k = 0; k < 4; k++) acc[i][j][k] = 0.f;

  for (int s = 0; s < NS; s++) {
    int pt = s / KCH, kk = s % KCH;
    if (s+1 < NS) { fill((s+1)&1, (s+1)/KCH, (s+1)%KCH); cp_commit(); cp_wait<1>(); }
    else          { cp_wait<0>(); }
    __syncthreads();
    uint32_t xbase = sXb + (uint32_t)((s&1)*32*72)*2;
#pragma unroll
    for (int ks = 0; ks < 2; ks++) {
      int wcol = kk*32 + ks*16 + (lane >> 4)*8;
      uint32_t a[MF][4];
#pragma unroll
      for (int mf = 0; mf < MF; mf++) {
        int row = wm*(COUT/4) + mf*16 + (lane & 15);
        ldsm4(a[mf], sWb + (uint32_t)(row*KP + wcol)*2);
      }
      uint32_t bf[2][4];
#pragma unroll
      for (int nb = 0; nb < 2; nb++) {
        int xrow = ks*16 + ((lane >> 3) & 1)*8 + (lane & 7);
        int ncol = wn*32 + nb*16 + (lane >> 4)*8;
        ldsm4t(bf[nb], xbase + (uint32_t)(xrow*72 + ncol)*2);
      }
#pragma unroll
      for (int mf = 0; mf < MF; mf++)
#pragma unroll
        for (int nf = 0; nf < 4; nf++)
          mma16816(acc[mf][nf], a[mf], bf[nf>>1][(nf&1)*2], bf[nf>>1][(nf&1)*2+1]);
    }
    if (kk == KCH-1) {
      int px = p0 + pt*64;
#pragma unroll
      for (int mf = 0; mf < MF; mf++) {
        int row = wm*(COUT/4) + mf*16 + (lane >> 2);
        float bv0 = __ldg(&A.bias[row]);
        float bv1 = __ldg(&A.bias[row+8]);
#pragma unroll
        for (int nf = 0; nf < 4; nf++) {
          int col = wn*32 + nf*8 + (lane & 3)*2;
          size_t o0 = ((size_t)b*COUT + row)*kHW + px + col;
          size_t o1 = o0 + (size_t)8*kHW;
          if (RES) {
            float2 r0 = *(const float2*)(A.res + o0);
            float2 r1 = *(const float2*)(A.res + o1);
            *(float2*)(A.outF + o0) = make_float2(acc[mf][nf][0]+bv0+r0.x, acc[mf][nf][1]+bv0+r0.y);
            *(float2*)(A.outF + o1) = make_float2(acc[mf][nf][2]+bv1+r1.x, acc[mf][nf][3]+bv1+r1.y);
          } else {
            *(__nv_bfloat162*)(A.outB + o0) = pack_bf2(acc[mf][nf][0]+bv0, acc[mf][nf][1]+bv0);
            *(__nv_bfloat162*)(A.outB + o1) = pack_bf2(acc[mf][nf][2]+bv1, acc[mf][nf][3]+bv1);
          }
          acc[mf][nf][0] = acc[mf][nf][1] = acc[mf][nf][2] = acc[mf][nf][3] = 0.f;
        }
      }
    }
    __syncthreads();
  }
}

// ---------------- depthwise 3x3 (remaining Q branch only) ----------------
__global__ __launch_bounds__(256) void dwconv_kernel(
    DwArgs d0, DwArgs d1, DwArgs d2, DwArgs d3, DwArgs d4) {
  DwArgs a = d0;
  int z = blockIdx.z;
  if (z == 1) a = d1; else if (z == 2) a = d2; else if (z == 3) a = d3; else if (z == 4) a = d4;

  int bc = blockIdx.y;
  int c  = bc & (kNC-1);
  int h0 = blockIdx.x * 8;
  const __nv_bfloat16* ip = a.in + (size_t)bc*kHW;
  __nv_bfloat16* op = a.out + (size_t)bc*kHW;
  __shared__ __nv_bfloat16 tile[10][400];
  int t = threadIdx.x;

  for (int i = t; i < 160; i += 256) {
    int r = i >> 4, j = i & 15;
    tile[r][(j < 8) ? j : 384 + j] = __float2bfloat16(0.f);
  }
  for (int i = t; i < 480; i += 256) {
    int r = i / 48, cg = i - r*48;
    int h = h0 - 1 + r;
    uint4 v = make_uint4(0u, 0u, 0u, 0u);
    if (h >= 0 && h < kH) v = *(const uint4*)(ip + (size_t)h*kW + cg*8);
    *(uint4*)&tile[r][8 + cg*8] = v;
  }
  __syncthreads();

  float wr[9];
#pragma unroll
  for (int j = 0; j < 9; j++) wr[j] = __ldg(&a.w[c*9 + j]);
  float bv = __ldg(&a.bias[c]);

#pragma unroll
  for (int i = 0; i < 6; i++) {
    int p = 2*(t + 256*i);
    int row = p / 384, x = p - row*384;
    float a0 = bv, a1 = bv;
#pragma unroll
    for (int dy = 0; dy < 3; dy++) {
      __nv_bfloat162 v0 = *(__nv_bfloat162*)&tile[row+dy][6 + x];
      __nv_bfloat162 v1 = *(__nv_bfloat162*)&tile[row+dy][8 + x];
      __nv_bfloat162 v2 = *(__nv_bfloat162*)&tile[row+dy][10 + x];
      float l  = __bfloat162float(v0.y);
      float c0 = __bfloat162float(v1.x);
      float c1 = __bfloat162float(v1.y);
      float r_ = __bfloat162float(v2.x);
      float w0 = wr[dy*3+0], w1 = wr[dy*3+1], w2 = wr[dy*3+2];
      a0 += w0*l  + w1*c0 + w2*c1;
      a1 += w0*c0 + w1*c1 + w2*r_;
    }
    *(__nv_bfloat162*)(op + (size_t)(h0+row)*kW + x) = pack_bf2(a0, a1);
  }
}

// ---------------- fused attention: O = softmax(Q K^T * scale) @ V ----------------
__global__ __launch_bounds__(128) void attn_kernel() {
  __shared__ __nv_bfloat16 sA[64*200];
  __shared__ __nv_bfloat16 sBuf[2*256*40];
  int bc = blockIdx.y, side = blockIdx.z;
  const __nv_bfloat16* qb = g_Qm + (size_t)bc*kHW;
  const __nv_bfloat16* km = (side == 0 ? g_Kr : g_Kl) + (size_t)bc*kHW;
  const __nv_bfloat16* vb = (side == 0 ? g_Vl : g_Vr) + (size_t)bc*kHW;
  __nv_bfloat16* ob = (side == 0 ? g_Ol : g_Or) + (size_t)bc*kHW;
  int m0 = blockIdx.x * 64;
  int t = threadIdx.x, warp = t >> 5, lane = t & 31;

  uint32_t sAb = (uint32_t)__cvta_generic_to_shared(sA);
  uint32_t sBb = (uint32_t)__cvta_generic_to_shared(sBuf);

  // ---- phase 1 ----
  {
    auto fillQK = [&](int buf, int kb) {
      const __nv_bfloat16* qsrc = qb + (size_t)m0*kW + kb*32;
      const __nv_bfloat16* ksrc = km + kb*32;
      for (int i = t; i < 1024; i += 128) {
        int row = i >> 2, cg = i & 3;
        const __nv_bfloat16* src = (row < 64) ? (qsrc + (size_t)row*kW + cg*8)
                                              : (ksrc + (size_t)(row-64)*kW + cg*8);
        cp16(sBb + (uint32_t)(buf*10240 + row*40 + cg*8)*2, src);
      }
    };

    fillQK(0, 0); cp_commit();

    float acc[24][4];
#pragma unroll
    for (int i = 0; i < 24; i++)
#pragma unroll
      for (int j = 0; j < 4; j++) acc[i][j] = 0.f;

    for (int kb = 0; kb < 12; kb++) {
      if (kb < 11) { fillQK((kb+1)&1, kb+1); cp_commit(); cp_wait<1>(); }
      else         { cp_wait<0>(); }
      __syncthreads();
      uint32_t qbase = sBb + (uint32_t)((kb&1)*10240)*2;
      uint32_t kbase = qbase + (uint32_t)(64*40)*2;
#pragma unroll
      for (int ks = 0; ks < 2; ks++) {
        int k0 = ks*16;
        uint32_t a[4];
        {
          int row = warp*16 + (lane & 15);
          int col = k0 + (lane >> 4)*8;
          ldsm4(a, qbase + (uint32_t)(row*40 + col)*2);
        }
        uint32_t bf[12][4];
#pragma unroll
        for (int nb = 0; nb < 12; nb++) {
          int nrow = nb*16 + (lane >> 4)*8 + (lane & 7);
          int col  = k0 + ((lane >> 3) & 1)*8;
          ldsm4(bf[nb], kbase + (uint32_t)(nrow*40 + col)*2);
        }
#pragma unroll
        for (int nf = 0; nf < 24; nf++)
          mma16816(acc[nf], a, bf[nf>>1][(nf&1)*2], bf[nf>>1][(nf&1)*2+1]);
      }
      __syncthreads();
    }

#pragma unroll
    for (int nf = 0; nf < 24; nf++)
#pragma unroll
      for (int j = 0; j < 4; j++) acc[nf][j] *= kScale;

    float mx0 = -1e30f, mx1 = -1e30f;
#pragma unroll
    for (int nf = 0; nf < 24; nf++) {
      mx0 = fmaxf(mx0, fmaxf(acc[nf][0], acc[nf][1]));
      mx1 = fmaxf(mx1, fmaxf(acc[nf][2], acc[nf][3]));
    }
#pragma unroll
    for (int o = 1; o <= 2; o <<= 1) {
      mx0 = fmaxf(mx0, __shfl_xor_sync(0xffffffffu, mx0, o));
      mx1 = fmaxf(mx1, __shfl_xor_sync(0xffffffffu, mx1, o));
    }
    float s0 = 0.f, s1 = 0.f;
#pragma unroll
    for (int nf = 0; nf < 24; nf++) {
      acc[nf][0] = __expf(acc[nf][0]-mx0); s0 += acc[nf][0];
      acc[nf][1] = __expf(acc[nf][1]-mx0); s0 += acc[nf][1];
      acc[nf][2] = __expf(acc[nf][2]-mx1); s1 += acc[nf][2];
      acc[nf][3] = __expf(acc[nf][3]-mx1); s1 += acc[nf][3];
    }
#pragma unroll
    for (int o = 1; o <= 2; o <<= 1) {
      s0 += __shfl_xor_sync(0xffffffffu, s0, o);
      s1 += __shfl_xor_sync(0xffffffffu, s1, o);
    }
    float i0 = 1.f/s0, i1 = 1.f/s1;

    int r0 = warp*16 + (lane >> 2);
#pragma unroll
    for (int nf = 0; nf < 24; nf++) {
      int c = nf*8 + (lane & 3)*2;
      *(__nv_bfloat162*)&sA[r0*200 + c]     = pack_bf2(acc[nf][0]*i0, acc[nf][1]*i0);
      *(__nv_bfloat162*)&sA[(r0+8)*200 + c] = pack_bf2(acc[nf][2]*i1, acc[nf][3]*i1);
    }
  }
  __syncthreads();

  // ---- phase 2 ----
  int wm = warp >> 1, wn = warp & 1;
#pragma unroll
  for (int n0 = 0; n0 < kW; n0 += 128) {
    float oac[2][8][4];
#pragma unroll
    for (int i = 0; i < 2; i++)
#pragma unroll
      for (int j = 0; j < 8; j++)
#pragma unroll
        for (int k = 0; k < 4; k++) oac[i][j][k] = 0.f;

    for (int i = t; i < 512; i += 128) {
      int row = i >> 4, cg = i & 15;
      cp16(sBb + (uint32_t)(row*136 + cg*8)*2, vb + (size_t)row*kW + n0 + cg*8);
    }
    cp_commit();

    for (int kc = 0; kc < 6; kc++) {
      if (kc < 5) {
        uint32_t dst = sBb + (uint32_t)(((kc+1)&1)*32*136)*2;
        const __nv_bfloat16* vsrc = vb + (size_t)(kc+1)*32*kW + n0;
        for (int i = t; i < 512; i += 128) {
          int row = i >> 4, cg = i & 15;
          cp16(dst + (uint32_t)(row*136 + cg*8)*2, vsrc + (size_t)row*kW + cg*8);
        }
        cp_commit();
        cp_wait<1>();
      } else {
        cp_wait<0>();
      }
      __syncthreads();
      uint32_t vbase = sBb + (uint32_t)((kc&1)*32*136)*2;
#pragma unroll
      for (int ks = 0; ks < 2; ks++) {
        int k0 = ks*16;
        uint32_t a[2][4];
#pragma unroll
        for (int mf = 0; mf < 2; mf++) {
          int row = wm*32 + mf*16 + (lane & 15);
          int col = kc*32 + k0 + (lane >> 4)*8;
          ldsm4(a[mf], sAb + (uint32_t)(row*200 + col)*2);
        }
        uint32_t b[4][4];
#pragma unroll
        for (int nb = 0; nb < 4; nb++) {
          int krow = k0 + ((lane >> 3) & 1)*8 + (lane & 7);
          int ncol = wn*64 + nb*16 + (lane >> 4)*8;
          ldsm4t(b[nb], vbase + (uint32_t)(krow*136 + ncol)*2);
        }
#pragma unroll
        for (int mf = 0; mf < 2; mf++)
#pragma unroll
          for (int nf = 0; nf < 8; nf++)
            mma16816(oac[mf][nf], a[mf], b[nf>>1][(nf&1)*2], b[nf>>1][(nf&1)*2+1]);
      }
      __syncthreads();
    }
#pragma unroll
    for (int mf = 0; mf < 2; mf++)
#pragma unroll
      for (int nf = 0; nf < 8; nf++) {
        int r = m0 + wm*32 + mf*16 + (lane >> 2);
        int c = n0 + wn*64 + nf*8 + (lane & 3)*2;
        *(__nv_bfloat162*)(ob + (size_t)r*kW + c)     = pack_bf2(oac[mf][nf][0], oac[mf][nf][1]);
        *(__nv_bfloat162*)(ob + (size_t)(r+8)*kW + c) = pack_bf2(oac[mf][nf][2], oac[mf][nf][3]);
      }
  }
}

// ---------------- launch ----------------
extern "C" void kernel_launch(void* const* d_in, const int* in_sizes, int n_in,
                              void* d_out, int out_size) {
  const float* x_l   = (const float*)d_in[0];
  const float* x_r   = (const float*)d_in[1];
  const float* ln1_g = (const float*)d_in[2];
  const float* ln1_b = (const float*)d_in[3];
  const float* ln2_g = (const float*)d_in[4];
  const float* ln2_b = (const float*)d_in[5];
  const float* w1 = (const float*)d_in[6];   const float* b1 = (const float*)d_in[7];
  const float* w2 = (const float*)d_in[8];   const float* b2 = (const float*)d_in[9];
  const float* w3 = (const float*)d_in[10];  const float* b3 = (const float*)d_in[11];
  const float* w4 = (const float*)d_in[12];  const float* b4 = (const float*)d_in[13];
  const float* w5 = (const float*)d_in[14];  const float* b5 = (const float*)d_in[15];
  const float* dw1 = (const float*)d_in[16]; const float* db1 = (const float*)d_in[17];
  const float* dw2 = (const float*)d_in[18]; const float* db2 = (const float*)d_in[19];
  const float* dw3 = (const float*)d_in[20]; const float* db3 = (const float*)d_in[21];
  const float* dw4 = (const float*)d_in[22]; const float* db4 = (const float*)d_in[23];
  const float* dw5 = (const float*)d_in[24]; const float* db5 = (const float*)d_in[25];
  const float* w6 = (const float*)d_in[26];  const float* b6 = (const float*)d_in[27];
  const float* w7 = (const float*)d_in[28];  const float* b7 = (const float*)d_in[29];
  float* out = (float*)d_out;

  __nv_bfloat16 *nl, *nr, *P2, *Vl, *Kl, *Qm, *Kr, *Vr, *Ol, *Or, *Wbf;
  cudaGetSymbolAddress((void**)&nl, g_nl);
  cudaGetSymbolAddress((void**)&nr, g_nr);
  cudaGetSymbolAddress((void**)&P2, g_P2);
  cudaGetSymbolAddress((void**)&Vl, g_Vl);
  cudaGetSymbolAddress((void**)&Kl, g_Kl);
  cudaGetSymbolAddress((void**)&Qm, g_Qm);
  cudaGetSymbolAddress((void**)&Kr, g_Kr);
  cudaGetSymbolAddress((void**)&Vr, g_Vr);
  cudaGetSymbolAddress((void**)&Ol, g_Ol);
  cudaGetSymbolAddress((void**)&Or, g_Or);
  cudaGetSymbolAddress((void**)&Wbf, g_Wbf);

  // 0. weights -> bf16 arena
  wconv_kernel<<<256, 256>>>(w1, w2, w3, w4, w5, w6, w7);

  // 1. LayerNorm2d (both sides)
  ln_kernel<<<dim3(kB*kHW/256, 2), 256>>>(x_l, x_r, ln1_g, ln1_b, ln2_g, ln2_b, nl, nr);

  // 2a. fused conv1x1+dwconv for the four K=64 branches -> Vl, Kl, Kr, Vr
  FArgs fA = { nl, Wbf,         b1, dw1, db1, Vl };
  FArgs fB = { nl, Wbf + 8192,  b2, dw2, db2, Kl };
  FArgs fC = { nr, Wbf + 32768, b4, dw4, db4, Kr };
  FArgs fD = { nr, Wbf + 40960, b5, dw5, db5, Vr };
  fused_conv_dw_kernel<<<dim3(192, 4, kB), 256>>>(fA, fB, fC, fD);

  // 2b. dual-input conv (w3) -> P2, then its dwconv -> Qm
  ConvArgs a3 = { nl, nr, Wbf + 16384, b3, nullptr, nullptr, P2 };
  conv1x1_mma_kernel<kNC, 2*kC, true, false><<<dim3(kHW/256, 1, kB), 256>>>(a3, a3, a3, a3);
  DwArgs dC = { P2, dw3, db3, Qm };
  dwconv_kernel<<<dim3(kH/8, kB*kNC, 1), 256>>>(dC, dC, dC, dC, dC);

  // 3. fused attention (S + softmax + O)
  attn_kernel<<<dim3(3, kB*kNC, 2), 128>>>();

  // 4. final conv1x1 + residual (both sides), fp32 out
  ConvArgs f0 = { Ol, nullptr, Wbf + 49152, b6, x_l, out, nullptr };
  ConvArgs f1 = { Or, nullptr, Wbf + 57344, b7, x_r, out + (size_t)kB*kC*kHW, nullptr };
  conv1x1_mma_kernel<kC, kNC, false, true><<<dim3(kHW/256, 2, kB), 256>>>(f0, f1, f0, f1);
}